// round 1
// baseline (speedup 1.0000x reference)
#include <cuda_runtime.h>
#include <math.h>

#define LL 2048
#define DD 2048
#define NH 32
#define NKV 8
#define HDIM 64
#define QKVN 3072   // 2048 (q) + 512 (k) + 512 (v)

// Scratch (static device arrays; no allocation allowed)
__device__ float g_qkv[LL * QKVN];    // [L, 3072]: q | k | v
__device__ float g_attn[LL * DD];     // [L, H*HD] attention output

// ---------------------------------------------------------------------------
// GEMM 128x128x8 tile, 8x8 microtile, 256 threads
// ---------------------------------------------------------------------------
__global__ __launch_bounds__(256) void gemm_qkv_kernel(
    const float* __restrict__ x, const float* __restrict__ wq,
    const float* __restrict__ wk, const float* __restrict__ wv)
{
    __shared__ float As[8][128];
    __shared__ float Bs[8][128];
    const int tid = threadIdx.y * 16 + threadIdx.x;
    const int r0 = blockIdx.y * 128;
    const int c0 = blockIdx.x * 128;

    // column-block -> which weight (boundaries 2048, 2560 both %128==0)
    const float* Bp; int ldb; int cb;
    if (c0 < 2048)      { Bp = wq; ldb = 2048; cb = c0; }
    else if (c0 < 2560) { Bp = wk; ldb = 512;  cb = c0 - 2048; }
    else                { Bp = wv; ldb = 512;  cb = c0 - 2560; }

    const int a_row = tid >> 1;          // 0..127
    const int a_k4  = (tid & 1) * 4;     // 0 or 4
    const int b_row = tid >> 5;          // 0..7
    const int b_c4  = (tid & 31) * 4;    // 0..124

    float acc[8][8];
#pragma unroll
    for (int i = 0; i < 8; i++)
#pragma unroll
        for (int j = 0; j < 8; j++) acc[i][j] = 0.f;

    for (int k0 = 0; k0 < DD; k0 += 8) {
        float4 av = *(const float4*)(x + (size_t)(r0 + a_row) * DD + k0 + a_k4);
        As[a_k4 + 0][a_row] = av.x;
        As[a_k4 + 1][a_row] = av.y;
        As[a_k4 + 2][a_row] = av.z;
        As[a_k4 + 3][a_row] = av.w;
        *(float4*)(&Bs[b_row][b_c4]) =
            *(const float4*)(Bp + (size_t)(k0 + b_row) * ldb + cb + b_c4);
        __syncthreads();
#pragma unroll
        for (int kk = 0; kk < 8; kk++) {
            float a[8], b[8];
            *(float4*)(a)     = *(const float4*)(&As[kk][threadIdx.y * 8]);
            *(float4*)(a + 4) = *(const float4*)(&As[kk][threadIdx.y * 8 + 4]);
            *(float4*)(b)     = *(const float4*)(&Bs[kk][threadIdx.x * 8]);
            *(float4*)(b + 4) = *(const float4*)(&Bs[kk][threadIdx.x * 8 + 4]);
#pragma unroll
            for (int i = 0; i < 8; i++)
#pragma unroll
                for (int j = 0; j < 8; j++)
                    acc[i][j] += a[i] * b[j];
        }
        __syncthreads();
    }
#pragma unroll
    for (int i = 0; i < 8; i++) {
        float* dst = g_qkv + (size_t)(r0 + threadIdx.y * 8 + i) * QKVN
                     + c0 + threadIdx.x * 8;
        *(float4*)(dst)     = make_float4(acc[i][0], acc[i][1], acc[i][2], acc[i][3]);
        *(float4*)(dst + 4) = make_float4(acc[i][4], acc[i][5], acc[i][6], acc[i][7]);
    }
}

__global__ __launch_bounds__(256) void gemm_out_kernel(
    const float* __restrict__ wo, float* __restrict__ outp)
{
    __shared__ float As[8][128];
    __shared__ float Bs[8][128];
    const int tid = threadIdx.y * 16 + threadIdx.x;
    const int r0 = blockIdx.y * 128;
    const int c0 = blockIdx.x * 128;

    const int a_row = tid >> 1;
    const int a_k4  = (tid & 1) * 4;
    const int b_row = tid >> 5;
    const int b_c4  = (tid & 31) * 4;

    float acc[8][8];
#pragma unroll
    for (int i = 0; i < 8; i++)
#pragma unroll
        for (int j = 0; j < 8; j++) acc[i][j] = 0.f;

    for (int k0 = 0; k0 < DD; k0 += 8) {
        float4 av = *(const float4*)(g_attn + (size_t)(r0 + a_row) * DD + k0 + a_k4);
        As[a_k4 + 0][a_row] = av.x;
        As[a_k4 + 1][a_row] = av.y;
        As[a_k4 + 2][a_row] = av.z;
        As[a_k4 + 3][a_row] = av.w;
        *(float4*)(&Bs[b_row][b_c4]) =
            *(const float4*)(wo + (size_t)(k0 + b_row) * DD + c0 + b_c4);
        __syncthreads();
#pragma unroll
        for (int kk = 0; kk < 8; kk++) {
            float a[8], b[8];
            *(float4*)(a)     = *(const float4*)(&As[kk][threadIdx.y * 8]);
            *(float4*)(a + 4) = *(const float4*)(&As[kk][threadIdx.y * 8 + 4]);
            *(float4*)(b)     = *(const float4*)(&Bs[kk][threadIdx.x * 8]);
            *(float4*)(b + 4) = *(const float4*)(&Bs[kk][threadIdx.x * 8 + 4]);
#pragma unroll
            for (int i = 0; i < 8; i++)
#pragma unroll
                for (int j = 0; j < 8; j++)
                    acc[i][j] += a[i] * b[j];
        }
        __syncthreads();
    }
#pragma unroll
    for (int i = 0; i < 8; i++) {
        float* dst = outp + (size_t)(r0 + threadIdx.y * 8 + i) * DD
                     + c0 + threadIdx.x * 8;
        *(float4*)(dst)     = make_float4(acc[i][0], acc[i][1], acc[i][2], acc[i][3]);
        *(float4*)(dst + 4) = make_float4(acc[i][4], acc[i][5], acc[i][6], acc[i][7]);
    }
}

// ---------------------------------------------------------------------------
// RoPE (in-place on q and k parts of g_qkv)
// ---------------------------------------------------------------------------
__global__ void rope_kernel(const float* __restrict__ fc, const float* __restrict__ fs)
{
    int idx = blockIdx.x * blockDim.x + threadIdx.x;
    const int total = LL * (NH + NKV) * (HDIM / 2);
    if (idx >= total) return;
    int i    = idx & 31;          // pair index within head dim
    int rem  = idx >> 5;
    int head = rem % (NH + NKV);
    int l    = rem / (NH + NKV);
    int col  = (head < NH) ? head * HDIM + 2 * i
                           : 2048 + (head - NH) * HDIM + 2 * i;
    float* p = g_qkv + (size_t)l * QKVN + col;
    float xr = p[0], xi = p[1];
    float c = fc[l * 32 + i], s = fs[l * 32 + i];
    p[0] = xr * c - xi * s;
    p[1] = xr * s + xi * c;
}

// ---------------------------------------------------------------------------
// Flash-style causal attention: 64x64 tiles, online softmax
// grid (q_tiles=32, heads=32), 256 threads
// ---------------------------------------------------------------------------
__global__ __launch_bounds__(256) void attn_kernel()
{
    const int qt = blockIdx.x;
    const int h  = blockIdx.y;
    const int kvh = h >> 2;   // REP=4

    extern __shared__ float sm[];
    float* qT  = sm;               // [64 d][64 q] (transposed)
    float* kT  = qT + 4096;        // [64 d][64 k]
    float* Vb  = kT + 4096;        // [64 k][64 d]
    float* S   = Vb + 4096;        // [64 q][65]   (padded)
    float* m_s = S + 64 * 65;
    float* l_s = m_s + 64;
    float* a_s = l_s + 64;

    const int tid  = threadIdx.x;
    const int tx   = tid & 15;
    const int ty   = tid >> 4;
    const int qrow = tid >> 2;     // 0..63 (quad per row)
    const int part = tid & 3;
    const int dbase = part * 16;

    // load Q tile transposed
#pragma unroll
    for (int it = 0; it < 4; it++) {
        int lin = tid + it * 256;           // float4 slot
        int row = lin >> 4;
        int c4  = (lin & 15) * 4;
        float4 v = *(const float4*)(g_qkv + (size_t)(qt * 64 + row) * QKVN + h * HDIM + c4);
        qT[(c4 + 0) * 64 + row] = v.x;
        qT[(c4 + 1) * 64 + row] = v.y;
        qT[(c4 + 2) * 64 + row] = v.z;
        qT[(c4 + 3) * 64 + row] = v.w;
    }
    if (tid < 64) { m_s[tid] = -1e30f; l_s[tid] = 0.f; }

    float acc[16];
#pragma unroll
    for (int d = 0; d < 16; d++) acc[d] = 0.f;

    for (int kt = 0; kt <= qt; kt++) {
        // load K (transposed) and V tiles for kv head
#pragma unroll
        for (int it = 0; it < 4; it++) {
            int lin = tid + it * 256;
            int row = lin >> 4;
            int c4  = (lin & 15) * 4;
            const float* base = g_qkv + (size_t)(kt * 64 + row) * QKVN;
            float4 kv = *(const float4*)(base + 2048 + kvh * HDIM + c4);
            kT[(c4 + 0) * 64 + row] = kv.x;
            kT[(c4 + 1) * 64 + row] = kv.y;
            kT[(c4 + 2) * 64 + row] = kv.z;
            kT[(c4 + 3) * 64 + row] = kv.w;
            *(float4*)(Vb + row * 64 + c4) =
                *(const float4*)(base + 2560 + kvh * HDIM + c4);
        }
        __syncthreads();

        // S = (q . k^T) * scale + causal mask
        float s4[4][4];
#pragma unroll
        for (int i = 0; i < 4; i++)
#pragma unroll
            for (int j = 0; j < 4; j++) s4[i][j] = 0.f;
        for (int d = 0; d < 64; d++) {
            float a[4], b[4];
            *(float4*)a = *(const float4*)(&qT[d * 64 + ty * 4]);
            *(float4*)b = *(const float4*)(&kT[d * 64 + tx * 4]);
#pragma unroll
            for (int i = 0; i < 4; i++)
#pragma unroll
                for (int j = 0; j < 4; j++)
                    s4[i][j] += a[i] * b[j];
        }
#pragma unroll
        for (int i = 0; i < 4; i++) {
#pragma unroll
            for (int j = 0; j < 4; j++) {
                int qi = qt * 64 + ty * 4 + i;
                int ki = kt * 64 + tx * 4 + j;
                float v = s4[i][j] * 0.125f + (ki > qi ? -1e9f : 0.f);
                S[(ty * 4 + i) * 65 + tx * 4 + j] = v;
            }
        }
        __syncthreads();

        // online softmax (quad of 4 threads per query row)
        float pm = -1e30f;
#pragma unroll
        for (int kk = 0; kk < 16; kk++)
            pm = fmaxf(pm, S[qrow * 65 + part * 16 + kk]);
        pm = fmaxf(pm, __shfl_xor_sync(0xffffffffu, pm, 1));
        pm = fmaxf(pm, __shfl_xor_sync(0xffffffffu, pm, 2));
        float m_old = m_s[qrow];
        float m_new = fmaxf(m_old, pm);
        float ps = 0.f;
#pragma unroll
        for (int kk = 0; kk < 16; kk++) {
            float e = __expf(S[qrow * 65 + part * 16 + kk] - m_new);
            S[qrow * 65 + part * 16 + kk] = e;
            ps += e;
        }
        ps += __shfl_xor_sync(0xffffffffu, ps, 1);
        ps += __shfl_xor_sync(0xffffffffu, ps, 2);
        if (part == 0) {
            float alpha = __expf(m_old - m_new);
            a_s[qrow] = alpha;
            l_s[qrow] = l_s[qrow] * alpha + ps;
            m_s[qrow] = m_new;
        }
        __syncwarp();

        // acc = acc*alpha + P @ V   (thread owns 16 dims of its row)
        float alpha = a_s[qrow];
#pragma unroll
        for (int d = 0; d < 16; d++) acc[d] *= alpha;
        for (int k = 0; k < 64; k++) {
            float p = S[qrow * 65 + k];
            const float4* vp = (const float4*)(Vb + k * 64 + dbase);
            float4 v0 = vp[0], v1 = vp[1], v2 = vp[2], v3 = vp[3];
            acc[0]  += p * v0.x; acc[1]  += p * v0.y; acc[2]  += p * v0.z; acc[3]  += p * v0.w;
            acc[4]  += p * v1.x; acc[5]  += p * v1.y; acc[6]  += p * v1.z; acc[7]  += p * v1.w;
            acc[8]  += p * v2.x; acc[9]  += p * v2.y; acc[10] += p * v2.z; acc[11] += p * v2.w;
            acc[12] += p * v3.x; acc[13] += p * v3.y; acc[14] += p * v3.z; acc[15] += p * v3.w;
        }
        __syncthreads();
    }

    float linv = 1.f / l_s[qrow];
    float* dst = g_attn + (size_t)(qt * 64 + qrow) * DD + h * HDIM + dbase;
#pragma unroll
    for (int d4 = 0; d4 < 4; d4++) {
        *(float4*)(dst + d4 * 4) = make_float4(acc[d4 * 4 + 0] * linv,
                                               acc[d4 * 4 + 1] * linv,
                                               acc[d4 * 4 + 2] * linv,
                                               acc[d4 * 4 + 3] * linv);
    }
}

// ---------------------------------------------------------------------------
extern "C" void kernel_launch(void* const* d_in, const int* in_sizes, int n_in,
                              void* d_out, int out_size)
{
    const float* x  = (const float*)d_in[0];
    const float* wq = (const float*)d_in[1];
    const float* wk = (const float*)d_in[2];
    const float* wv = (const float*)d_in[3];
    const float* wo = (const float*)d_in[4];
    const float* fc = (const float*)d_in[5];
    const float* fs = (const float*)d_in[6];
    // d_in[7] = mask (unused; causal mask computed inline, identical -1e9 value)
    float* outp = (float*)d_out;

    dim3 blk(16, 16);
    gemm_qkv_kernel<<<dim3(24, 16), blk>>>(x, wq, wk, wv);

    int total = LL * (NH + NKV) * (HDIM / 2);
    rope_kernel<<<(total + 255) / 256, 256>>>(fc, fs);

    const int smem = (4096 * 3 + 64 * 65 + 192) * 4;  // 66560 B
    cudaFuncSetAttribute(attn_kernel, cudaFuncAttributeMaxDynamicSharedMemorySize, smem);
    attn_kernel<<<dim3(32, 32), 256, smem>>>();

    gemm_out_kernel<<<dim3(16, 16), blk>>>(wo, outp);
}

// round 2
// speedup vs baseline: 2.1516x; 2.1516x over previous
#include <cuda_runtime.h>
#include <mma.h>
#include <math.h>

using namespace nvcuda;

#define LL 2048
#define DD 2048
#define NH 32
#define NKV 8
#define HDIM 64
#define QKVN 3072

__device__ float g_qkv[LL * QKVN];
__device__ float g_attn[LL * DD];

// ---------------------------------------------------------------------------
// tf32 WMMA GEMM: 128x128 block tile, KC=32, 8 warps, warp tile 32x64
// ---------------------------------------------------------------------------
#define KC 32
#define A_LD 40    // 128 x 40 floats (160B rows, 32B-aligned)
#define B_LD 136   // 32 x 136 floats

typedef wmma::fragment<wmma::matrix_a, 16, 16, 8, wmma::precision::tf32, wmma::row_major> AFrag;
typedef wmma::fragment<wmma::matrix_b, 16, 16, 8, wmma::precision::tf32, wmma::row_major> BFrag;
typedef wmma::fragment<wmma::matrix_b, 16, 16, 8, wmma::precision::tf32, wmma::col_major> BFragT;
typedef wmma::fragment<wmma::accumulator, 16, 16, 8, float> CFrag;

__device__ __forceinline__ void frag_to_tf32(float* x, int n) {
#pragma unroll
    for (int t = 0; t < n; t++) x[t] = wmma::__float_to_tf32(x[t]);
}

// A [2048 x 2048] = src, B per column block, C = dst with ldc
__device__ __forceinline__ void gemm_tile_tf32(
    const float* __restrict__ A, const float* __restrict__ Bp, int ldb, int cb,
    float* __restrict__ C, int ldc, int r0, int c0)
{
    __shared__ float As[128 * A_LD];
    __shared__ float Bs[KC * B_LD];

    const int tid = threadIdx.x;
    const int w = tid >> 5;
    const int warp_m = w & 3;       // 0..3  (32-row slabs)
    const int warp_n = w >> 2;      // 0..1  (64-col slabs)

    CFrag acc[2][4];
#pragma unroll
    for (int i = 0; i < 2; i++)
#pragma unroll
        for (int j = 0; j < 4; j++) wmma::fill_fragment(acc[i][j], 0.f);

    for (int k0 = 0; k0 < DD; k0 += KC) {
        // load A 128x32
#pragma unroll
        for (int it = 0; it < 4; it++) {
            int lin = tid + it * 256;          // float4 slot, 1024 total
            int row = lin >> 3;
            int c4  = (lin & 7) * 4;
            float4 v = *(const float4*)(A + (size_t)(r0 + row) * DD + k0 + c4);
            *(float4*)(&As[row * A_LD + c4]) = v;
        }
        // load B 32x128
#pragma unroll
        for (int it = 0; it < 4; it++) {
            int lin = tid + it * 256;
            int row = lin >> 5;
            int c4  = (lin & 31) * 4;
            float4 v = *(const float4*)(Bp + (size_t)(k0 + row) * ldb + cb + c4);
            *(float4*)(&Bs[row * B_LD + c4]) = v;
        }
        __syncthreads();

#pragma unroll
        for (int ks = 0; ks < KC / 8; ks++) {
            AFrag a[2];
            BFrag b[4];
#pragma unroll
            for (int i = 0; i < 2; i++) {
                wmma::load_matrix_sync(a[i], &As[(warp_m * 32 + i * 16) * A_LD + ks * 8], A_LD);
                frag_to_tf32(a[i].x, a[i].num_elements);
            }
#pragma unroll
            for (int j = 0; j < 4; j++) {
                wmma::load_matrix_sync(b[j], &Bs[(ks * 8) * B_LD + warp_n * 64 + j * 16], B_LD);
                frag_to_tf32(b[j].x, b[j].num_elements);
            }
#pragma unroll
            for (int i = 0; i < 2; i++)
#pragma unroll
                for (int j = 0; j < 4; j++)
                    wmma::mma_sync(acc[i][j], a[i], b[j], acc[i][j]);
        }
        __syncthreads();
    }

#pragma unroll
    for (int i = 0; i < 2; i++)
#pragma unroll
        for (int j = 0; j < 4; j++)
            wmma::store_matrix_sync(
                C + (size_t)(r0 + warp_m * 32 + i * 16) * ldc + c0 + warp_n * 64 + j * 16,
                acc[i][j], ldc, wmma::mem_row_major);
}

__global__ __launch_bounds__(256) void gemm_qkv_kernel(
    const float* __restrict__ x, const float* __restrict__ wq,
    const float* __restrict__ wk, const float* __restrict__ wv)
{
    const int r0 = blockIdx.y * 128;
    const int c0 = blockIdx.x * 128;
    const float* Bp; int ldb; int cb;
    if (c0 < 2048)      { Bp = wq; ldb = 2048; cb = c0; }
    else if (c0 < 2560) { Bp = wk; ldb = 512;  cb = c0 - 2048; }
    else                { Bp = wv; ldb = 512;  cb = c0 - 2560; }
    gemm_tile_tf32(x, Bp, ldb, cb, g_qkv, QKVN, r0, c0);
}

__global__ __launch_bounds__(256) void gemm_out_kernel(
    const float* __restrict__ wo, float* __restrict__ outp)
{
    gemm_tile_tf32(g_attn, wo, DD, blockIdx.x * 128, outp, DD,
                   blockIdx.y * 128, blockIdx.x * 128);
}

// ---------------------------------------------------------------------------
// RoPE (in-place)
// ---------------------------------------------------------------------------
__global__ void rope_kernel(const float* __restrict__ fc, const float* __restrict__ fs)
{
    int idx = blockIdx.x * blockDim.x + threadIdx.x;
    const int total = LL * (NH + NKV) * (HDIM / 2);
    if (idx >= total) return;
    int i    = idx & 31;
    int rem  = idx >> 5;
    int head = rem % (NH + NKV);
    int l    = rem / (NH + NKV);
    int col  = (head < NH) ? head * HDIM + 2 * i
                           : 2048 + (head - NH) * HDIM + 2 * i;
    float* p = g_qkv + (size_t)l * QKVN + col;
    float xr = p[0], xi = p[1];
    float c = fc[l * 32 + i], s = fs[l * 32 + i];
    p[0] = xr * c - xi * s;
    p[1] = xr * s + xi * c;
}

// ---------------------------------------------------------------------------
// Flash attention, 64x64 tiles, tf32 WMMA for S=QK^T and O+=P*V
// grid (32 q-tiles, 32 heads), 256 threads (8 warps)
// ---------------------------------------------------------------------------
#define T_LD 72    // 288B rows (32B-aligned)

__global__ __launch_bounds__(256) void attn_kernel()
{
    const int qt = blockIdx.x;
    const int h  = blockIdx.y;
    const int kvh = h >> 2;

    extern __shared__ float sm[];
    float* Qs = sm;                    // [64][T_LD]  (pre-scaled by 1/8)
    float* Ks = Qs + 64 * T_LD;        // [64][T_LD]
    float* Vs = Ks + 64 * T_LD;        // [64][T_LD]
    float* Ss = Vs + 64 * T_LD;        // [64][T_LD]  scores / P
    float* Os = Ss + 64 * T_LD;        // [64][T_LD]  output accumulator
    float* m_s = Os + 64 * T_LD;
    float* l_s = m_s + 64;
    float* a_s = l_s + 64;

    const int tid = threadIdx.x;
    const int w = tid >> 5;
    const int warp_m = w & 3;
    const int warp_n = w >> 2;
    const int qrow = tid >> 2;
    const int part = tid & 3;

    // load Q (scaled)
#pragma unroll
    for (int it = 0; it < 4; it++) {
        int lin = tid + it * 256;
        int row = lin >> 4;
        int c4  = (lin & 15) * 4;
        float4 v = *(const float4*)(g_qkv + (size_t)(qt * 64 + row) * QKVN + h * HDIM + c4);
        *(float4*)(&Qs[row * T_LD + c4]) =
            make_float4(v.x * 0.125f, v.y * 0.125f, v.z * 0.125f, v.w * 0.125f);
    }
    // zero O
#pragma unroll
    for (int it = 0; it < 16; it++) {
        int lin = tid + it * 256;
        Os[(lin >> 6) * T_LD + (lin & 63)] = 0.f;
    }
    if (tid < 64) { m_s[tid] = -1e30f; l_s[tid] = 0.f; }
    __syncthreads();

    for (int kt = 0; kt <= qt; kt++) {
        // load K, V
#pragma unroll
        for (int it = 0; it < 4; it++) {
            int lin = tid + it * 256;
            int row = lin >> 4;
            int c4  = (lin & 15) * 4;
            const float* base = g_qkv + (size_t)(kt * 64 + row) * QKVN;
            *(float4*)(&Ks[row * T_LD + c4]) = *(const float4*)(base + 2048 + kvh * HDIM + c4);
            *(float4*)(&Vs[row * T_LD + c4]) = *(const float4*)(base + 2560 + kvh * HDIM + c4);
        }
        __syncthreads();

        // S = Qs @ Ks^T  (Ks row-major == K^T col-major)
        {
            CFrag sacc[2];
            wmma::fill_fragment(sacc[0], 0.f);
            wmma::fill_fragment(sacc[1], 0.f);
            // warp computes rows warp_m*16? -> need 4x4=16 tiles over 8 warps: 2 per warp.
            // tile (tm, tn): tm = warp_m (0..3), tn = warp_n*2 + {0,1}
#pragma unroll
            for (int ks = 0; ks < 8; ks++) {
                AFrag a;
                wmma::load_matrix_sync(a, &Qs[(warp_m * 16) * T_LD + ks * 8], T_LD);
                frag_to_tf32(a.x, a.num_elements);
#pragma unroll
                for (int j = 0; j < 2; j++) {
                    BFragT b;
                    wmma::load_matrix_sync(b, &Ks[((warp_n * 2 + j) * 16) * T_LD + ks * 8], T_LD);
                    frag_to_tf32(b.x, b.num_elements);
                    wmma::mma_sync(sacc[j], a, b, sacc[j]);
                }
            }
#pragma unroll
            for (int j = 0; j < 2; j++)
                wmma::store_matrix_sync(&Ss[(warp_m * 16) * T_LD + (warp_n * 2 + j) * 16],
                                        sacc[j], T_LD, wmma::mem_row_major);
        }
        __syncthreads();

        // online softmax (quad per row), causal mask inline on diagonal tile
        {
            const bool diag = (kt == qt);
            float vals[16];
            float pm = -1e30f;
#pragma unroll
            for (int kk = 0; kk < 16; kk++) {
                float v = Ss[qrow * T_LD + part * 16 + kk];
                if (diag && (part * 16 + kk > qrow)) v = -1e30f;
                vals[kk] = v;
                pm = fmaxf(pm, v);
            }
            pm = fmaxf(pm, __shfl_xor_sync(0xffffffffu, pm, 1));
            pm = fmaxf(pm, __shfl_xor_sync(0xffffffffu, pm, 2));
            float m_old = m_s[qrow];
            float m_new = fmaxf(m_old, pm);
            float ps = 0.f;
#pragma unroll
            for (int kk = 0; kk < 16; kk++) {
                float e = __expf(vals[kk] - m_new);
                Ss[qrow * T_LD + part * 16 + kk] = e;
                ps += e;
            }
            ps += __shfl_xor_sync(0xffffffffu, ps, 1);
            ps += __shfl_xor_sync(0xffffffffu, ps, 2);
            if (part == 0) {
                float alpha = __expf(m_old - m_new);
                a_s[qrow] = alpha;
                l_s[qrow] = l_s[qrow] * alpha + ps;
                m_s[qrow] = m_new;
            }
        }
        __syncthreads();

        // rescale O rows by alpha
#pragma unroll
        for (int it = 0; it < 16; it++) {
            int lin = tid + it * 256;
            int row = lin >> 6;
            Os[row * T_LD + (lin & 63)] *= a_s[row];
        }
        __syncthreads();

        // O += P @ V  (P = Ss [64 q][64 k], V = Vs [64 k][64 d])
        {
#pragma unroll
            for (int j = 0; j < 2; j++) {
                CFrag oacc;
                wmma::load_matrix_sync(oacc, &Os[(warp_m * 16) * T_LD + (warp_n * 2 + j) * 16],
                                       T_LD, wmma::mem_row_major);
#pragma unroll
                for (int ks = 0; ks < 8; ks++) {
                    AFrag a;
                    wmma::load_matrix_sync(a, &Ss[(warp_m * 16) * T_LD + ks * 8], T_LD);
                    frag_to_tf32(a.x, a.num_elements);
                    BFrag b;
                    wmma::load_matrix_sync(b, &Vs[(ks * 8) * T_LD + (warp_n * 2 + j) * 16], T_LD);
                    frag_to_tf32(b.x, b.num_elements);
                    wmma::mma_sync(oacc, a, b, oacc);
                }
                wmma::store_matrix_sync(&Os[(warp_m * 16) * T_LD + (warp_n * 2 + j) * 16],
                                        oacc, T_LD, wmma::mem_row_major);
            }
        }
        __syncthreads();
    }

    // final normalize + write
#pragma unroll
    for (int it = 0; it < 16; it++) {
        int lin = tid + it * 256;
        int row = lin >> 6;
        int col = lin & 63;
        g_attn[(size_t)(qt * 64 + row) * DD + h * HDIM + col] =
            Os[row * T_LD + col] / l_s[row];
    }
}

// ---------------------------------------------------------------------------
extern "C" void kernel_launch(void* const* d_in, const int* in_sizes, int n_in,
                              void* d_out, int out_size)
{
    const float* x  = (const float*)d_in[0];
    const float* wq = (const float*)d_in[1];
    const float* wk = (const float*)d_in[2];
    const float* wv = (const float*)d_in[3];
    const float* wo = (const float*)d_in[4];
    const float* fc = (const float*)d_in[5];
    const float* fs = (const float*)d_in[6];
    float* outp = (float*)d_out;

    gemm_qkv_kernel<<<dim3(24, 16), 256>>>(x, wq, wk, wv);

    int total = LL * (NH + NKV) * (HDIM / 2);
    rope_kernel<<<(total + 255) / 256, 256>>>(fc, fs);

    const int smem = (5 * 64 * T_LD + 192) * 4;   // 93,696 B
    static bool attr_set = false;
    if (!attr_set) {
        cudaFuncSetAttribute(attn_kernel, cudaFuncAttributeMaxDynamicSharedMemorySize, smem);
        attr_set = true;
    }
    attn_kernel<<<dim3(32, 32), 256, smem>>>();

    gemm_out_kernel<<<dim3(16, 16), 256>>>(wo, outp);
}

// round 4
// speedup vs baseline: 2.5498x; 1.1851x over previous
#include <cuda_runtime.h>
#include <mma.h>
#include <math.h>

using namespace nvcuda;

#define LL 2048
#define DD 2048
#define NH 32
#define NKV 8
#define HDIM 64
#define QKVN 3072

__device__ float g_qkv[LL * QKVN];
__device__ float g_attn[LL * DD];

// ---------------------------------------------------------------------------
// cp.async helpers
// ---------------------------------------------------------------------------
__device__ __forceinline__ void cp_async16(void* smem, const void* gmem) {
    unsigned saddr = (unsigned)__cvta_generic_to_shared(smem);
    asm volatile("cp.async.cg.shared.global [%0], [%1], 16;\n" :: "r"(saddr), "l"(gmem));
}
__device__ __forceinline__ void cp_commit() {
    asm volatile("cp.async.commit_group;\n");
}
template <int N>
__device__ __forceinline__ void cp_wait() {
    asm volatile("cp.async.wait_group %0;\n" :: "n"(N));
}

// ---------------------------------------------------------------------------
// WMMA typedefs (tf32, m16n16k8)
// ---------------------------------------------------------------------------
typedef wmma::fragment<wmma::matrix_a, 16, 16, 8, wmma::precision::tf32, wmma::row_major> AFrag;
typedef wmma::fragment<wmma::matrix_b, 16, 16, 8, wmma::precision::tf32, wmma::row_major> BFrag;
typedef wmma::fragment<wmma::matrix_b, 16, 16, 8, wmma::precision::tf32, wmma::col_major> BFragT;
typedef wmma::fragment<wmma::accumulator, 16, 16, 8, float> CFrag;

__device__ __forceinline__ void frag_to_tf32(float* x, int n) {
#pragma unroll
    for (int t = 0; t < n; t++) x[t] = wmma::__float_to_tf32(x[t]);
}

// ---------------------------------------------------------------------------
// Double-buffered tf32 GEMM: 128x128 tile, KC=32, 256 threads, 8 warps (32x64)
// ---------------------------------------------------------------------------
#define KC 32
#define A_LD 40
#define B_LD 136
#define GEMM_SMEM ((2 * 128 * A_LD + 2 * KC * B_LD) * 4)  // 75,776 B

__device__ __forceinline__ void gemm_pipe(
    const float* __restrict__ A, const float* __restrict__ Bp, int ldb, int cb,
    float* __restrict__ C, int ldc, int r0, int c0)
{
    extern __shared__ float sh[];
    float* As = sh;                     // [2][128*A_LD]
    float* Bs = sh + 2 * 128 * A_LD;    // [2][KC*B_LD]

    const int tid = threadIdx.x;
    const int w = tid >> 5;
    const int wm = w & 3;
    const int wn = w >> 2;

    CFrag acc[2][4];
#pragma unroll
    for (int i = 0; i < 2; i++)
#pragma unroll
        for (int j = 0; j < 4; j++) wmma::fill_fragment(acc[i][j], 0.f);

#define G_LOAD_STAGE(s, k0)                                                         \
    do {                                                                            \
        _Pragma("unroll") for (int it = 0; it < 4; it++) {                          \
            int lin = tid + it * 256;                                               \
            int row = lin >> 3;                                                     \
            int c4 = (lin & 7) * 4;                                                 \
            cp_async16(&As[(s) * 128 * A_LD + row * A_LD + c4],                     \
                       A + (size_t)(r0 + row) * DD + (k0) + c4);                    \
        }                                                                           \
        _Pragma("unroll") for (int it = 0; it < 4; it++) {                          \
            int lin = tid + it * 256;                                               \
            int row = lin >> 5;                                                     \
            int c4 = (lin & 31) * 4;                                                \
            cp_async16(&Bs[(s) * KC * B_LD + row * B_LD + c4],                      \
                       Bp + (size_t)((k0) + row) * ldb + cb + c4);                  \
        }                                                                           \
    } while (0)

    G_LOAD_STAGE(0, 0);
    cp_commit();

    int s = 0;
    for (int k0 = 0; k0 < DD; k0 += KC, s ^= 1) {
        if (k0 + KC < DD) G_LOAD_STAGE(s ^ 1, k0 + KC);
        cp_commit();
        cp_wait<1>();
        __syncthreads();

        const float* Ab = &As[s * 128 * A_LD];
        const float* Bb = &Bs[s * KC * B_LD];
#pragma unroll
        for (int ks = 0; ks < 4; ks++) {
            AFrag a[2];
            BFrag b[4];
#pragma unroll
            for (int i = 0; i < 2; i++) {
                wmma::load_matrix_sync(a[i], Ab + (wm * 32 + i * 16) * A_LD + ks * 8, A_LD);
                frag_to_tf32(a[i].x, a[i].num_elements);
            }
#pragma unroll
            for (int j = 0; j < 4; j++) {
                wmma::load_matrix_sync(b[j], Bb + (ks * 8) * B_LD + wn * 64 + j * 16, B_LD);
                frag_to_tf32(b[j].x, b[j].num_elements);
            }
#pragma unroll
            for (int i = 0; i < 2; i++)
#pragma unroll
                for (int j = 0; j < 4; j++)
                    wmma::mma_sync(acc[i][j], a[i], b[j], acc[i][j]);
        }
        __syncthreads();
    }

#pragma unroll
    for (int i = 0; i < 2; i++)
#pragma unroll
        for (int j = 0; j < 4; j++)
            wmma::store_matrix_sync(
                C + (size_t)(r0 + wm * 32 + i * 16) * ldc + c0 + wn * 64 + j * 16,
                acc[i][j], ldc, wmma::mem_row_major);
#undef G_LOAD_STAGE
}

__global__ __launch_bounds__(256) void gemm_qkv_kernel(
    const float* __restrict__ x, const float* __restrict__ wq,
    const float* __restrict__ wk, const float* __restrict__ wv)
{
    const int r0 = blockIdx.y * 128;
    const int c0 = blockIdx.x * 128;
    const float* Bp; int ldb; int cb;
    if (c0 < 2048)      { Bp = wq; ldb = 2048; cb = c0; }
    else if (c0 < 2560) { Bp = wk; ldb = 512;  cb = c0 - 2048; }
    else                { Bp = wv; ldb = 512;  cb = c0 - 2560; }
    gemm_pipe(x, Bp, ldb, cb, g_qkv, QKVN, r0, c0);
}

__global__ __launch_bounds__(256) void gemm_out_kernel(
    const float* __restrict__ wo, float* __restrict__ outp)
{
    gemm_pipe(g_attn, wo, DD, blockIdx.x * 128, outp, DD,
              blockIdx.y * 128, blockIdx.x * 128);
}

// ---------------------------------------------------------------------------
// RoPE (in-place)
// ---------------------------------------------------------------------------
__global__ void rope_kernel(const float* __restrict__ fc, const float* __restrict__ fs)
{
    int idx = blockIdx.x * blockDim.x + threadIdx.x;
    const int total = LL * (NH + NKV) * (HDIM / 2);
    if (idx >= total) return;
    int i    = idx & 31;
    int rem  = idx >> 5;
    int head = rem % (NH + NKV);
    int l    = rem / (NH + NKV);
    int col  = (head < NH) ? head * HDIM + 2 * i
                           : 2048 + (head - NH) * HDIM + 2 * i;
    float* p = g_qkv + (size_t)l * QKVN + col;
    float xr = p[0], xi = p[1];
    float c = fc[l * 32 + i], s = fs[l * 32 + i];
    p[0] = xr * c - xi * s;
    p[1] = xr * s + xi * c;
}

// ---------------------------------------------------------------------------
// Flash attention: 128-row Q tile x 64-col K tiles, 512 threads (16 warps),
// tf32 WMMA, double-buffered cp.async K/V.
// grid (head=32, qt=16 reversed), warp tile: 16 rows x 32 cols
// ---------------------------------------------------------------------------
#define T_LD 72
#define ATT_SMEM ((3 * 128 * T_LD + 4 * 64 * T_LD + 3 * 128) * 4)  // 185,856 B

__global__ __launch_bounds__(512) void attn_kernel()
{
    const int h   = blockIdx.x;
    const int qt  = (gridDim.y - 1) - blockIdx.y;   // big tiles first
    const int kvh = h >> 2;

    extern __shared__ float sm[];
    float* Qs = sm;                      // [128][T_LD] (pre-scaled)
    float* Ss = Qs + 128 * T_LD;         // [128][T_LD]
    float* Os = Ss + 128 * T_LD;         // [128][T_LD]
    float* Ks = Os + 128 * T_LD;         // [2][64][T_LD]
    float* Vs = Ks + 2 * 64 * T_LD;      // [2][64][T_LD]
    float* m_s = Vs + 2 * 64 * T_LD;     // [128]
    float* l_s = m_s + 128;
    float* a_s = l_s + 128;

    const int tid = threadIdx.x;
    const int w  = tid >> 5;
    const int wm = w & 7;        // 16-row slab
    const int wn = w >> 3;       // 32-col slab
    const int qrow = tid >> 2;   // 0..127
    const int part = tid & 3;

#define A_LOAD_KV(s, kt)                                                            \
    do {                                                                            \
        const float* base0 = g_qkv + (size_t)((kt) * 64) * QKVN;                    \
        _Pragma("unroll") for (int it = 0; it < 2; it++) {                          \
            int lin = tid + it * 512;                                               \
            int row = lin >> 4;                                                     \
            int c4 = (lin & 15) * 4;                                                \
            const float* rb = base0 + (size_t)row * QKVN;                           \
            cp_async16(&Ks[(s) * 64 * T_LD + row * T_LD + c4],                      \
                       rb + 2048 + kvh * HDIM + c4);                                \
            cp_async16(&Vs[(s) * 64 * T_LD + row * T_LD + c4],                      \
                       rb + 2560 + kvh * HDIM + c4);                                \
        }                                                                           \
    } while (0)

    // kick off K/V tile 0
    A_LOAD_KV(0, 0);
    cp_commit();

    // load Q (scaled by 1/8)
#pragma unroll
    for (int it = 0; it < 4; it++) {
        int lin = tid + it * 512;
        int row = lin >> 4;
        int c4  = (lin & 15) * 4;
        float4 v = *(const float4*)(g_qkv + (size_t)(qt * 128 + row) * QKVN + h * HDIM + c4);
        *(float4*)(&Qs[row * T_LD + c4]) =
            make_float4(v.x * 0.125f, v.y * 0.125f, v.z * 0.125f, v.w * 0.125f);
    }
    // zero O
#pragma unroll
    for (int it = 0; it < 16; it++) {
        int lin = tid + it * 512;
        Os[(lin >> 6) * T_LD + (lin & 63)] = 0.f;
    }
    if (tid < 128) { m_s[tid] = -1e30f; l_s[tid] = 0.f; }

    const int nkt = 2 * qt + 2;
    int s = 0;
    for (int kt = 0; kt < nkt; kt++, s ^= 1) {
        if (kt + 1 < nkt) A_LOAD_KV(s ^ 1, kt + 1);
        cp_commit();
        cp_wait<1>();
        __syncthreads();

        const float* Kb = &Ks[s * 64 * T_LD];
        const float* Vb = &Vs[s * 64 * T_LD];

        // S = Qs @ K^T
        {
            CFrag sacc[2];
            wmma::fill_fragment(sacc[0], 0.f);
            wmma::fill_fragment(sacc[1], 0.f);
#pragma unroll
            for (int ks = 0; ks < 8; ks++) {
                AFrag a;
                wmma::load_matrix_sync(a, &Qs[(wm * 16) * T_LD + ks * 8], T_LD);
                frag_to_tf32(a.x, a.num_elements);
#pragma unroll
                for (int j = 0; j < 2; j++) {
                    BFragT b;
                    wmma::load_matrix_sync(b, Kb + (wn * 32 + j * 16) * T_LD + ks * 8, T_LD);
                    frag_to_tf32(b.x, b.num_elements);
                    wmma::mma_sync(sacc[j], a, b, sacc[j]);
                }
            }
#pragma unroll
            for (int j = 0; j < 2; j++)
                wmma::store_matrix_sync(&Ss[(wm * 16) * T_LD + wn * 32 + j * 16],
                                        sacc[j], T_LD, wmma::mem_row_major);
        }
        __syncthreads();

        // online softmax: quad of 4 threads per row, 16 cols each
        {
            const bool tail = (kt >= 2 * qt);
            const int qi = qt * 128 + qrow;
            float vals[16];
            float pm = -1e30f;
#pragma unroll
            for (int kk = 0; kk < 16; kk++) {
                float v = Ss[qrow * T_LD + part * 16 + kk];
                if (tail && (kt * 64 + part * 16 + kk > qi)) v = -1e30f;
                vals[kk] = v;
                pm = fmaxf(pm, v);
            }
            pm = fmaxf(pm, __shfl_xor_sync(0xffffffffu, pm, 1));
            pm = fmaxf(pm, __shfl_xor_sync(0xffffffffu, pm, 2));
            float m_old = m_s[qrow];
            float m_new = fmaxf(m_old, pm);
            float ps = 0.f;
#pragma unroll
            for (int kk = 0; kk < 16; kk++) {
                float e = __expf(vals[kk] - m_new);
                Ss[qrow * T_LD + part * 16 + kk] = e;
                ps += e;
            }
            ps += __shfl_xor_sync(0xffffffffu, ps, 1);
            ps += __shfl_xor_sync(0xffffffffu, ps, 2);
            if (part == 0) {
                float alpha = __expf(m_old - m_new);
                a_s[qrow] = alpha;
                l_s[qrow] = l_s[qrow] * alpha + ps;
                m_s[qrow] = m_new;
            }
        }
        __syncthreads();

        // rescale O
#pragma unroll
        for (int it = 0; it < 16; it++) {
            int lin = tid + it * 512;
            int row = lin >> 6;
            Os[row * T_LD + (lin & 63)] *= a_s[row];
        }
        __syncthreads();

        // O += P @ V
        {
#pragma unroll
            for (int j = 0; j < 2; j++) {
                CFrag oacc;
                wmma::load_matrix_sync(oacc, &Os[(wm * 16) * T_LD + wn * 32 + j * 16],
                                       T_LD, wmma::mem_row_major);
#pragma unroll
                for (int ks = 0; ks < 8; ks++) {
                    AFrag a;
                    wmma::load_matrix_sync(a, &Ss[(wm * 16) * T_LD + ks * 8], T_LD);
                    frag_to_tf32(a.x, a.num_elements);
                    BFrag b;
                    wmma::load_matrix_sync(b, Vb + (ks * 8) * T_LD + wn * 32 + j * 16, T_LD);
                    frag_to_tf32(b.x, b.num_elements);
                    wmma::mma_sync(oacc, a, b, oacc);
                }
                wmma::store_matrix_sync(&Os[(wm * 16) * T_LD + wn * 32 + j * 16],
                                        oacc, T_LD, wmma::mem_row_major);
            }
        }
        __syncthreads();
    }

    // final normalize + write
#pragma unroll
    for (int it = 0; it < 16; it++) {
        int lin = tid + it * 512;
        int row = lin >> 6;
        int col = lin & 63;
        g_attn[(size_t)(qt * 128 + row) * DD + h * HDIM + col] =
            Os[row * T_LD + col] / l_s[row];
    }
#undef A_LOAD_KV
}

// ---------------------------------------------------------------------------
extern "C" void kernel_launch(void* const* d_in, const int* in_sizes, int n_in,
                              void* d_out, int out_size)
{
    const float* x  = (const float*)d_in[0];
    const float* wq = (const float*)d_in[1];
    const float* wk = (const float*)d_in[2];
    const float* wv = (const float*)d_in[3];
    const float* wo = (const float*)d_in[4];
    const float* fc = (const float*)d_in[5];
    const float* fs = (const float*)d_in[6];
    float* outp = (float*)d_out;

    cudaFuncSetAttribute(gemm_qkv_kernel, cudaFuncAttributeMaxDynamicSharedMemorySize, GEMM_SMEM);
    cudaFuncSetAttribute(gemm_out_kernel, cudaFuncAttributeMaxDynamicSharedMemorySize, GEMM_SMEM);
    cudaFuncSetAttribute(attn_kernel, cudaFuncAttributeMaxDynamicSharedMemorySize, ATT_SMEM);

    gemm_qkv_kernel<<<dim3(24, 16), 256, GEMM_SMEM>>>(x, wq, wk, wv);

    int total = LL * (NH + NKV) * (HDIM / 2);
    rope_kernel<<<(total + 255) / 256, 256>>>(fc, fs);

    attn_kernel<<<dim3(32, 16), 512, ATT_SMEM>>>();

    gemm_out_kernel<<<dim3(16, 16), 256, GEMM_SMEM>>>(wo, outp);
}

// round 8
// speedup vs baseline: 2.7920x; 1.0950x over previous
#include <cuda_runtime.h>
#include <mma.h>
#include <math.h>

using namespace nvcuda;

#define LL 2048
#define DD 2048
#define NH 32
#define NKV 8
#define HDIM 64
#define QKVN 3072

__device__ float g_qkv[LL * QKVN];
__device__ float g_attn[LL * DD];

// ---------------------------------------------------------------------------
// cp.async helpers
// ---------------------------------------------------------------------------
__device__ __forceinline__ void cp_async16(void* smem, const void* gmem) {
    unsigned saddr = (unsigned)__cvta_generic_to_shared(smem);
    asm volatile("cp.async.cg.shared.global [%0], [%1], 16;\n" :: "r"(saddr), "l"(gmem));
}
__device__ __forceinline__ void cp_commit() {
    asm volatile("cp.async.commit_group;\n");
}
template <int N>
__device__ __forceinline__ void cp_wait() {
    asm volatile("cp.async.wait_group %0;\n" :: "n"(N));
}

// ---------------------------------------------------------------------------
// WMMA typedefs (tf32, m16n16k8)
// ---------------------------------------------------------------------------
typedef wmma::fragment<wmma::matrix_a, 16, 16, 8, wmma::precision::tf32, wmma::row_major> AFrag;
typedef wmma::fragment<wmma::matrix_b, 16, 16, 8, wmma::precision::tf32, wmma::row_major> BFrag;
typedef wmma::fragment<wmma::matrix_b, 16, 16, 8, wmma::precision::tf32, wmma::col_major> BFragT;
typedef wmma::fragment<wmma::accumulator, 16, 16, 8, float> CFrag;

__device__ __forceinline__ void frag_to_tf32(float* x, int n) {
#pragma unroll
    for (int t = 0; t < n; t++) x[t] = wmma::__float_to_tf32(x[t]);
}

// ---------------------------------------------------------------------------
// Double-buffered tf32 GEMM: 128x128 tile, KC=32, 256 threads, 8 warps (32x64)
// 2 CTAs/SM (launch_bounds caps regs at 128)
// ---------------------------------------------------------------------------
#define KC 32
#define A_LD 40
#define B_LD 136
#define GEMM_SMEM ((2 * 128 * A_LD + 2 * KC * B_LD) * 4)  // 75,776 B

__device__ __forceinline__ void gemm_pipe(
    const float* __restrict__ A, const float* __restrict__ Bp, int ldb, int cb,
    float* __restrict__ C, int ldc, int r0, int c0)
{
    extern __shared__ float sh[];
    float* As = sh;
    float* Bs = sh + 2 * 128 * A_LD;

    const int tid = threadIdx.x;
    const int w = tid >> 5;
    const int wm = w & 3;
    const int wn = w >> 2;

    CFrag acc[2][4];
#pragma unroll
    for (int i = 0; i < 2; i++)
#pragma unroll
        for (int j = 0; j < 4; j++) wmma::fill_fragment(acc[i][j], 0.f);

#define G_LOAD_STAGE(s, k0)                                                         \
    do {                                                                            \
        _Pragma("unroll") for (int it = 0; it < 4; it++) {                          \
            int lin = tid + it * 256;                                               \
            int row = lin >> 3;                                                     \
            int c4 = (lin & 7) * 4;                                                 \
            cp_async16(&As[(s) * 128 * A_LD + row * A_LD + c4],                     \
                       A + (size_t)(r0 + row) * DD + (k0) + c4);                    \
        }                                                                           \
        _Pragma("unroll") for (int it = 0; it < 4; it++) {                          \
            int lin = tid + it * 256;                                               \
            int row = lin >> 5;                                                     \
            int c4 = (lin & 31) * 4;                                                \
            cp_async16(&Bs[(s) * KC * B_LD + row * B_LD + c4],                      \
                       Bp + (size_t)((k0) + row) * ldb + cb + c4);                  \
        }                                                                           \
    } while (0)

    G_LOAD_STAGE(0, 0);
    cp_commit();

    int s = 0;
    for (int k0 = 0; k0 < DD; k0 += KC, s ^= 1) {
        if (k0 + KC < DD) G_LOAD_STAGE(s ^ 1, k0 + KC);
        cp_commit();
        cp_wait<1>();
        __syncthreads();

        const float* Ab = &As[s * 128 * A_LD];
        const float* Bb = &Bs[s * KC * B_LD];
#pragma unroll
        for (int ks = 0; ks < 4; ks++) {
            AFrag a[2];
            BFrag b[4];
#pragma unroll
            for (int i = 0; i < 2; i++) {
                wmma::load_matrix_sync(a[i], Ab + (wm * 32 + i * 16) * A_LD + ks * 8, A_LD);
                frag_to_tf32(a[i].x, a[i].num_elements);
            }
#pragma unroll
            for (int j = 0; j < 4; j++) {
                wmma::load_matrix_sync(b[j], Bb + (ks * 8) * B_LD + wn * 64 + j * 16, B_LD);
                frag_to_tf32(b[j].x, b[j].num_elements);
            }
#pragma unroll
            for (int i = 0; i < 2; i++)
#pragma unroll
                for (int j = 0; j < 4; j++)
                    wmma::mma_sync(acc[i][j], a[i], b[j], acc[i][j]);
        }
        __syncthreads();
    }

#pragma unroll
    for (int i = 0; i < 2; i++)
#pragma unroll
        for (int j = 0; j < 4; j++)
            wmma::store_matrix_sync(
                C + (size_t)(r0 + wm * 32 + i * 16) * ldc + c0 + wn * 64 + j * 16,
                acc[i][j], ldc, wmma::mem_row_major);
#undef G_LOAD_STAGE
}

__global__ __launch_bounds__(256, 2) void gemm_qkv_kernel(
    const float* __restrict__ x, const float* __restrict__ wq,
    const float* __restrict__ wk, const float* __restrict__ wv)
{
    const int r0 = blockIdx.y * 128;
    const int c0 = blockIdx.x * 128;
    const float* Bp; int ldb; int cb;
    if (c0 < 2048)      { Bp = wq; ldb = 2048; cb = c0; }
    else if (c0 < 2560) { Bp = wk; ldb = 512;  cb = c0 - 2048; }
    else                { Bp = wv; ldb = 512;  cb = c0 - 2560; }
    gemm_pipe(x, Bp, ldb, cb, g_qkv, QKVN, r0, c0);
}

__global__ __launch_bounds__(256, 2) void gemm_out_kernel(
    const float* __restrict__ wo, float* __restrict__ outp)
{
    gemm_pipe(g_attn, wo, DD, blockIdx.x * 128, outp, DD,
              blockIdx.y * 128, blockIdx.x * 128);
}

// ---------------------------------------------------------------------------
// RoPE (in-place)
// ---------------------------------------------------------------------------
__global__ void rope_kernel(const float* __restrict__ fc, const float* __restrict__ fs)
{
    int idx = blockIdx.x * blockDim.x + threadIdx.x;
    const int total = LL * (NH + NKV) * (HDIM / 2);
    if (idx >= total) return;
    int i    = idx & 31;
    int rem  = idx >> 5;
    int head = rem % (NH + NKV);
    int l    = rem / (NH + NKV);
    int col  = (head < NH) ? head * HDIM + 2 * i
                           : 2048 + (head - NH) * HDIM + 2 * i;
    float* p = g_qkv + (size_t)l * QKVN + col;
    float xr = p[0], xi = p[1];
    float c = fc[l * 32 + i], s = fs[l * 32 + i];
    p[0] = xr * c - xi * s;
    p[1] = xr * s + xi * c;
}

// ---------------------------------------------------------------------------
// Flash attention: 128-row Q tile x 64-col K tiles, 512 threads (16 warps),
// tf32 WMMA, double-buffered cp.async K/V. Softmax pass also rescales O
// in-place (quad owns row slice), saving one pass + one sync per tile.
// ---------------------------------------------------------------------------
#define T_LD 72
#define ATT_SMEM ((3 * 128 * T_LD + 4 * 64 * T_LD + 2 * 128) * 4)

__global__ __launch_bounds__(512) void attn_kernel()
{
    const int h   = blockIdx.x;
    const int qt  = (gridDim.y - 1) - blockIdx.y;   // big tiles first
    const int kvh = h >> 2;

    extern __shared__ float sm[];
    float* Qs = sm;                      // [128][T_LD] (pre-scaled)
    float* Ss = Qs + 128 * T_LD;         // [128][T_LD]
    float* Os = Ss + 128 * T_LD;         // [128][T_LD]
    float* Ks = Os + 128 * T_LD;         // [2][64][T_LD]
    float* Vs = Ks + 2 * 64 * T_LD;      // [2][64][T_LD]
    float* m_s = Vs + 2 * 64 * T_LD;     // [128]
    float* l_s = m_s + 128;

    const int tid = threadIdx.x;
    const int w  = tid >> 5;
    const int wm = w & 7;        // 16-row slab
    const int wn = w >> 3;       // 32-col slab
    const int qrow = tid >> 2;   // 0..127
    const int part = tid & 3;

#define A_LOAD_KV(s, kt)                                                            \
    do {                                                                            \
        const float* base0 = g_qkv + (size_t)((kt) * 64) * QKVN;                    \
        _Pragma("unroll") for (int it = 0; it < 2; it++) {                          \
            int lin = tid + it * 512;                                               \
            int row = lin >> 4;                                                     \
            int c4 = (lin & 15) * 4;                                                \
            const float* rb = base0 + (size_t)row * QKVN;                           \
            cp_async16(&Ks[(s) * 64 * T_LD + row * T_LD + c4],                      \
                       rb + 2048 + kvh * HDIM + c4);                                \
            cp_async16(&Vs[(s) * 64 * T_LD + row * T_LD + c4],                      \
                       rb + 2560 + kvh * HDIM + c4);                                \
        }                                                                           \
    } while (0)

    A_LOAD_KV(0, 0);
    cp_commit();

    // load Q (scaled by 1/8)
#pragma unroll
    for (int it = 0; it < 4; it++) {
        int lin = tid + it * 512;
        int row = lin >> 4;
        int c4  = (lin & 15) * 4;
        float4 v = *(const float4*)(g_qkv + (size_t)(qt * 128 + row) * QKVN + h * HDIM + c4);
        *(float4*)(&Qs[row * T_LD + c4]) =
            make_float4(v.x * 0.125f, v.y * 0.125f, v.z * 0.125f, v.w * 0.125f);
    }
    // zero O
#pragma unroll
    for (int it = 0; it < 16; it++) {
        int lin = tid + it * 512;
        Os[(lin >> 6) * T_LD + (lin & 63)] = 0.f;
    }
    if (tid < 128) { m_s[tid] = -1e30f; l_s[tid] = 0.f; }

    const int nkt = 2 * qt + 2;
    int s = 0;
    for (int kt = 0; kt < nkt; kt++, s ^= 1) {
        if (kt + 1 < nkt) A_LOAD_KV(s ^ 1, kt + 1);
        cp_commit();
        cp_wait<1>();
        __syncthreads();

        const float* Kb = &Ks[s * 64 * T_LD];
        const float* Vb = &Vs[s * 64 * T_LD];

        // S = Qs @ K^T
        {
            CFrag sacc[2];
            wmma::fill_fragment(sacc[0], 0.f);
            wmma::fill_fragment(sacc[1], 0.f);
#pragma unroll
            for (int ks = 0; ks < 8; ks++) {
                AFrag a;
                wmma::load_matrix_sync(a, &Qs[(wm * 16) * T_LD + ks * 8], T_LD);
                frag_to_tf32(a.x, a.num_elements);
#pragma unroll
                for (int j = 0; j < 2; j++) {
                    BFragT b;
                    wmma::load_matrix_sync(b, Kb + (wn * 32 + j * 16) * T_LD + ks * 8, T_LD);
                    frag_to_tf32(b.x, b.num_elements);
                    wmma::mma_sync(sacc[j], a, b, sacc[j]);
                }
            }
#pragma unroll
            for (int j = 0; j < 2; j++)
                wmma::store_matrix_sync(&Ss[(wm * 16) * T_LD + wn * 32 + j * 16],
                                        sacc[j], T_LD, wmma::mem_row_major);
        }
        __syncthreads();

        // online softmax + O rescale: quad of 4 threads per row, 16 cols each
        {
            const bool tail = (kt >= 2 * qt);
            const int qi = qt * 128 + qrow;
            float vals[16];
            float pm = -1e30f;
#pragma unroll
            for (int kk = 0; kk < 16; kk++) {
                float v = Ss[qrow * T_LD + part * 16 + kk];
                if (tail && (kt * 64 + part * 16 + kk > qi)) v = -1e30f;
                vals[kk] = v;
                pm = fmaxf(pm, v);
            }
            pm = fmaxf(pm, __shfl_xor_sync(0xffffffffu, pm, 1));
            pm = fmaxf(pm, __shfl_xor_sync(0xffffffffu, pm, 2));
            float m_old = m_s[qrow];
            float m_new = fmaxf(m_old, pm);
            float ps = 0.f;
#pragma unroll
            for (int kk = 0; kk < 16; kk++) {
                float e = __expf(vals[kk] - m_new);
                Ss[qrow * T_LD + part * 16 + kk] = e;
                ps += e;
            }
            ps += __shfl_xor_sync(0xffffffffu, ps, 1);
            ps += __shfl_xor_sync(0xffffffffu, ps, 2);
            float alpha = __expf(m_old - m_new);
            // each quad thread rescales its own 16-col slice of row qrow
#pragma unroll
            for (int kk = 0; kk < 16; kk++)
                Os[qrow * T_LD + part * 16 + kk] *= alpha;
            if (part == 0) {
                l_s[qrow] = l_s[qrow] * alpha + ps;
                m_s[qrow] = m_new;
            }
        }
        __syncthreads();

        // O += P @ V
        {
#pragma unroll
            for (int j = 0; j < 2; j++) {
                CFrag oacc;
                wmma::load_matrix_sync(oacc, &Os[(wm * 16) * T_LD + wn * 32 + j * 16],
                                       T_LD, wmma::mem_row_major);
#pragma unroll
                for (int ks = 0; ks < 8; ks++) {
                    AFrag a;
                    wmma::load_matrix_sync(a, &Ss[(wm * 16) * T_LD + ks * 8], T_LD);
                    frag_to_tf32(a.x, a.num_elements);
                    BFrag b;
                    wmma::load_matrix_sync(b, Vb + (ks * 8) * T_LD + wn * 32 + j * 16, T_LD);
                    frag_to_tf32(b.x, b.num_elements);
                    wmma::mma_sync(oacc, a, b, oacc);
                }
                wmma::store_matrix_sync(&Os[(wm * 16) * T_LD + wn * 32 + j * 16],
                                        oacc, T_LD, wmma::mem_row_major);
            }
        }
        __syncthreads();
    }

    // final normalize + write
#pragma unroll
    for (int it = 0; it < 16; it++) {
        int lin = tid + it * 512;
        int row = lin >> 6;
        int col = lin & 63;
        g_attn[(size_t)(qt * 128 + row) * DD + h * HDIM + col] =
            Os[row * T_LD + col] / l_s[row];
    }
#undef A_LOAD_KV
}

// ---------------------------------------------------------------------------
extern "C" void kernel_launch(void* const* d_in, const int* in_sizes, int n_in,
                              void* d_out, int out_size)
{
    const float* x  = (const float*)d_in[0];
    const float* wq = (const float*)d_in[1];
    const float* wk = (const float*)d_in[2];
    const float* wv = (const float*)d_in[3];
    const float* wo = (const float*)d_in[4];
    const float* fc = (const float*)d_in[5];
    const float* fs = (const float*)d_in[6];
    float* outp = (float*)d_out;

    cudaFuncSetAttribute(gemm_qkv_kernel, cudaFuncAttributeMaxDynamicSharedMemorySize, GEMM_SMEM);
    cudaFuncSetAttribute(gemm_out_kernel, cudaFuncAttributeMaxDynamicSharedMemorySize, GEMM_SMEM);
    cudaFuncSetAttribute(attn_kernel, cudaFuncAttributeMaxDynamicSharedMemorySize, ATT_SMEM);

    gemm_qkv_kernel<<<dim3(24, 16), 256, GEMM_SMEM>>>(x, wq, wk, wv);

    int total = LL * (NH + NKV) * (HDIM / 2);
    rope_kernel<<<(total + 255) / 256, 256>>>(fc, fs);

    attn_kernel<<<dim3(32, 16), 512, ATT_SMEM>>>();

    gemm_out_kernel<<<dim3(16, 16), 256, GEMM_SMEM>>>(wo, outp);
}